// round 5
// baseline (speedup 1.0000x reference)
#include <cuda_runtime.h>
#include <cuda_bf16.h>
#include <math.h>
#include <stdint.h>

#define CB   256   // batch
#define CN   77    // tokens
#define CD   768   // token dim
#define CK   16    // nodes
#define CDn  768   // node dim
#define CHID 512   // edge hidden
#define CL   2     // gnn layers

#define GK     768          // shared inner dim of all GEMMs
#define KCH    128          // int8 K elems per chunk (128B rows)
#define NCHUNK (GK / KCH)   // 6
#define TILEB  16384        // one 128x128 int8 tile in smem
#define BUFB   (4 * TILEB)  // Aq1, Aq2, Bq1, Bq2
#define NSTAGE 3
#define GSMEM  (NSTAGE * BUFB)  // 196608

// ---------------- scratch (device globals; no allocation allowed) ----------
__device__ float g_Kt[CB * CN * CDn];
__device__ float g_Vt[CB * CN * CDn];
__device__ float g_Q [CK * CDn];
__device__ float g_Qp[8 * CK * CDn];
__device__ float g_A [CB * CK * CK];
__device__ float g_H [CB * CK * 2 * CHID];   // [4096, 1024]: Hi | Hj
__device__ float g_Mg[CB * CK * CDn];
// int8 quantized operands
__device__ int8_t g_wq1[CB * CN * CDn];
__device__ int8_t g_wq2[CB * CN * CDn];
__device__ float  g_sa [CB * CN];
__device__ int8_t g_vq1[CB * CK * CDn];
__device__ int8_t g_vq2[CB * CK * CDn];
__device__ float  g_sv [CB * CK];
// transposed weights [4096, 768]: Wk(0) Wv(768) We1a(1536) We1b(2048) Wg0(2560) Wg1(3328)
__device__ int8_t g_Wq1[4096 * GK];
__device__ int8_t g_Wq2[4096 * GK];
__device__ float  g_sw [4096];

// ---------------- PTX helpers ----------------------------------------------
__device__ __forceinline__ uint32_t smem_u32(const void* p) {
    uint32_t a;
    asm("{ .reg .u64 t; cvta.to.shared.u64 t, %1; cvt.u32.u64 %0, t; }" : "=r"(a) : "l"(p));
    return a;
}
__device__ __forceinline__ void cpa16(uint32_t sa, const void* ga) {
    asm volatile("cp.async.cg.shared.global [%0], [%1], 16;" :: "r"(sa), "l"(ga));
}
__device__ __forceinline__ void ldsm4(uint32_t* r, uint32_t addr) {
    asm volatile("ldmatrix.sync.aligned.m8n8.x4.shared.b16 {%0,%1,%2,%3}, [%4];"
                 : "=r"(r[0]), "=r"(r[1]), "=r"(r[2]), "=r"(r[3]) : "r"(addr));
}
__device__ __forceinline__ void mma_s8(int* c, const uint32_t* a, uint32_t b0, uint32_t b1) {
    asm volatile(
        "mma.sync.aligned.m16n8k32.row.col.s32.s8.s8.s32 "
        "{%0,%1,%2,%3}, {%4,%5,%6,%7}, {%8,%9}, {%0,%1,%2,%3};"
        : "+r"(c[0]), "+r"(c[1]), "+r"(c[2]), "+r"(c[3])
        : "r"(a[0]), "r"(a[1]), "r"(a[2]), "r"(a[3]), "r"(b0), "r"(b1));
}

// ---------------- quantization kernels ---------------------------------------
// per-row 2-limb int8 quantization: x = s*(q1 + q2/128), s = rowmax/127
__global__ void aquant(const float* __restrict__ x, int8_t* __restrict__ q1,
                       int8_t* __restrict__ q2, float* __restrict__ sc)
{
    __shared__ float wm[8];
    __shared__ float ssc;
    int r = blockIdx.x;
    const float* row = x + (size_t)r * GK;
    int tid = threadIdx.x, lane = tid & 31, w = tid >> 5;
    float m = 0.f;
    for (int i = tid; i < GK; i += 256) m = fmaxf(m, fabsf(row[i]));
#pragma unroll
    for (int off = 16; off; off >>= 1) m = fmaxf(m, __shfl_xor_sync(0xffffffffu, m, off));
    if (lane == 0) wm[w] = m;
    __syncthreads();
    if (tid == 0) {
        float mm = 0.f;
#pragma unroll
        for (int i = 0; i < 8; i++) mm = fmaxf(mm, wm[i]);
        float s = mm / 127.f;
        if (s == 0.f) s = 1.f;
        ssc = s;
        sc[r] = s;
    }
    __syncthreads();
    float inv = 1.f / ssc;
    for (int i = tid; i < GK; i += 256) {
        float v = row[i] * inv;
        float f1 = rintf(v);
        float f2 = rintf((v - f1) * 128.f);
        q1[(size_t)r * GK + i] = (int8_t)(int)f1;
        q2[(size_t)r * GK + i] = (int8_t)(int)f2;
    }
}

// transposed weight quantization: dst row n = column n of W[768, ncols]
__global__ void wquant(const float* __restrict__ Wk, const float* __restrict__ Wv,
                       const float* __restrict__ We1, const float* __restrict__ Wg,
                       int8_t* __restrict__ q1, int8_t* __restrict__ q2,
                       float* __restrict__ sc)
{
    int z = blockIdx.y;
    const float* src; int ld, ncols, dsto;
    switch (z) {
        case 0: src = Wk;                        ld = 768; ncols = 768; dsto = 0;    break;
        case 1: src = Wv;                        ld = 768; ncols = 768; dsto = 768;  break;
        case 2: src = We1;                       ld = 512; ncols = 512; dsto = 1536; break;
        case 3: src = We1 + (size_t)768 * 512;   ld = 512; ncols = 512; dsto = 2048; break;
        case 4: src = Wg;                        ld = 768; ncols = 768; dsto = 2560; break;
        default: src = Wg + (size_t)768 * 768;   ld = 768; ncols = 768; dsto = 3328; break;
    }
    int w = threadIdx.x >> 5, lane = threadIdx.x & 31;
    int col0 = blockIdx.x * 32 + w * 4;
#pragma unroll
    for (int cc = 0; cc < 4; cc++) {
        int col = col0 + cc;
        if (col >= ncols) continue;
        float v[GK / 32];
        float m = 0.f;
#pragma unroll
        for (int j = 0; j < GK / 32; j++) {
            v[j] = src[(size_t)(lane + 32 * j) * ld + col];
            m = fmaxf(m, fabsf(v[j]));
        }
#pragma unroll
        for (int off = 16; off; off >>= 1) m = fmaxf(m, __shfl_xor_sync(0xffffffffu, m, off));
        float s = m / 127.f;
        if (s == 0.f) s = 1.f;
        float inv = 1.f / s;
#pragma unroll
        for (int j = 0; j < GK / 32; j++) {
            float t = v[j] * inv;
            float f1 = rintf(t);
            float f2 = rintf((t - f1) * 128.f);
            size_t o = (size_t)(dsto + col) * GK + lane + 32 * j;
            q1[o] = (int8_t)(int)f1;
            q2[o] = (int8_t)(int)f2;
        }
        if (lane == 0) sc[dsto + col] = s;
    }
}

// ---------------- int8 2-limb mma.sync GEMM ----------------------------------
// C[M,Nn] = sa[m]*sb[n]*(Q1A.Q1B^T + (Q1A.Q2B^T + Q2A.Q1B^T)/128) + bias
__global__ void __launch_bounds__(256, 1) gemm_i8(
    const int8_t* __restrict__ Aq1, const int8_t* __restrict__ Aq2,
    const float* __restrict__ sa,
    const int8_t* __restrict__ Bq1, const int8_t* __restrict__ Bq2,
    const float* __restrict__ sb,
    const float* __restrict__ bias, float* __restrict__ C, int Nn)
{
    extern __shared__ char smem[];
    const uint32_t sbase = smem_u32(smem);
    const int tid = threadIdx.x;
    const int lane = tid & 31, wid = tid >> 5;
    const int warp_m = wid >> 2, warp_n = wid & 3;   // 2 x 4 warp grid
    const int row0 = blockIdx.y * 128;
    const int col0 = blockIdx.x * 128;

    int acc1[4][4][4];
    int acc2[4][4][4];
#pragma unroll
    for (int a = 0; a < 4; a++)
#pragma unroll
        for (int b = 0; b < 4; b++)
#pragma unroll
            for (int c = 0; c < 4; c++) { acc1[a][b][c] = 0; acc2[a][b][c] = 0; }

#define ISSUE_CHUNK(chunk, buf)                                                     \
    do {                                                                            \
        uint32_t bufo_ = sbase + (buf) * BUFB;                                      \
        _Pragma("unroll")                                                           \
        for (int it = 0; it < 16; it++) {                                           \
            int idx_ = it * 256 + tid;                                              \
            int t_ = idx_ >> 10;                                                    \
            int r_ = (idx_ >> 3) & 127;                                             \
            int c_ = idx_ & 7;                                                      \
            const int8_t* sp_ =                                                     \
                (t_ == 0) ? Aq1 + (size_t)(row0 + r_) * GK :                        \
                (t_ == 1) ? Aq2 + (size_t)(row0 + r_) * GK :                        \
                (t_ == 2) ? Bq1 + (size_t)(col0 + r_) * GK :                        \
                            Bq2 + (size_t)(col0 + r_) * GK;                         \
            sp_ += (chunk) * KCH + c_ * 16;                                         \
            uint32_t sa_ = bufo_ + t_ * TILEB + r_ * 128 + ((c_ ^ (r_ & 7)) << 4);  \
            cpa16(sa_, sp_);                                                        \
        }                                                                           \
        asm volatile("cp.async.commit_group;" ::: "memory");                        \
    } while (0)

    ISSUE_CHUNK(0, 0);
    ISSUE_CHUNK(1, 1);

    const int rA  = warp_m * 64 + (lane & 15);
    const int khA = lane >> 4;
    const int rB  = warp_n * 32 + (lane & 7) + ((lane >> 4) << 3);
    const int khB = (lane >> 3) & 1;
    const int swA = rA & 7, swB = rB & 7;

    for (int i = 0; i < NCHUNK; i++) {
        if (i + 2 < NCHUNK) {
            ISSUE_CHUNK(i + 2, (i + 2) % NSTAGE);
            asm volatile("cp.async.wait_group 2;" ::: "memory");
        } else if (i + 1 < NCHUNK) {
            asm volatile("cp.async.wait_group 1;" ::: "memory");
        } else {
            asm volatile("cp.async.wait_group 0;" ::: "memory");
        }
        __syncthreads();
        uint32_t bufo = sbase + (i % NSTAGE) * BUFB;
#pragma unroll
        for (int kk = 0; kk < 4; kk++) {        // 4 x k32 per 128B chunk
            uint32_t a[2][4][4];                // [limb][mtile][reg]
            uint32_t b[2][2][4];                // [limb][ntile16][reg]
            int ckA = kk * 2 + khA;
            int ckB = kk * 2 + khB;
#pragma unroll
            for (int mt = 0; mt < 4; mt++) {
                uint32_t ad = bufo + (rA + mt * 16) * 128 + (((ckA ^ swA)) << 4);
                ldsm4(a[0][mt], ad);                 // Aq1
                ldsm4(a[1][mt], ad + TILEB);         // Aq2
            }
#pragma unroll
            for (int nt = 0; nt < 2; nt++) {
                uint32_t bd = bufo + 2 * TILEB + (rB + nt * 16) * 128 + (((ckB ^ swB)) << 4);
                ldsm4(b[0][nt], bd);                 // Bq1
                ldsm4(b[1][nt], bd + TILEB);         // Bq2
            }
#pragma unroll
            for (int mt = 0; mt < 4; mt++)
#pragma unroll
                for (int ng = 0; ng < 4; ng++) {
                    uint32_t b0q1 = b[0][ng >> 1][(ng & 1) * 2 + 0];
                    uint32_t b1q1 = b[0][ng >> 1][(ng & 1) * 2 + 1];
                    uint32_t b0q2 = b[1][ng >> 1][(ng & 1) * 2 + 0];
                    uint32_t b1q2 = b[1][ng >> 1][(ng & 1) * 2 + 1];
                    mma_s8(acc1[mt][ng], a[0][mt], b0q1, b1q1);   // q1*p1
                    mma_s8(acc2[mt][ng], a[0][mt], b0q2, b1q2);   // q1*p2
                    mma_s8(acc2[mt][ng], a[1][mt], b0q1, b1q1);   // q2*p1
                }
        }
        __syncthreads();
    }

    const int rowE = row0 + warp_m * 64 + (lane >> 2);
    const float inv128 = 1.f / 128.f;
#pragma unroll
    for (int mt = 0; mt < 4; mt++) {
        float sa0 = sa[rowE + mt * 16];
        float sa1 = sa[rowE + mt * 16 + 8];
#pragma unroll
        for (int ng = 0; ng < 4; ng++) {
            int col = col0 + warp_n * 32 + ng * 8 + 2 * (lane & 3);
            float sb0 = sb[col], sb1 = sb[col + 1];
            float b0 = bias ? bias[col + 0] : 0.f;
            float b1 = bias ? bias[col + 1] : 0.f;
            float2 v0, v1;
            v0.x = sa0 * sb0 * ((float)acc1[mt][ng][0] + (float)acc2[mt][ng][0] * inv128) + b0;
            v0.y = sa0 * sb1 * ((float)acc1[mt][ng][1] + (float)acc2[mt][ng][1] * inv128) + b1;
            v1.x = sa1 * sb0 * ((float)acc1[mt][ng][2] + (float)acc2[mt][ng][2] * inv128) + b0;
            v1.y = sa1 * sb1 * ((float)acc1[mt][ng][3] + (float)acc2[mt][ng][3] * inv128) + b1;
            *(float2*)(C + (size_t)(rowE + mt * 16) * Nn + col) = v0;
            *(float2*)(C + (size_t)(rowE + mt * 16 + 8) * Nn + col) = v1;
        }
    }
#undef ISSUE_CHUNK
}

// ---------------- Q = nq @ Wq + bq: partial over e-ranges, then reduce -----
__global__ void q_partial(const float* __restrict__ nq, const float* __restrict__ Wq,
                          float* __restrict__ Qp)
{
    int d = blockIdx.x * 128 + threadIdx.x;
    int e0 = blockIdx.y * 96;
    float acc[CK] = {};
    for (int e = e0; e < e0 + 96; e++) {
        float wv = Wq[(size_t)e * CDn + d];
#pragma unroll
        for (int k = 0; k < CK; k++) acc[k] += nq[k * CDn + e] * wv;
    }
#pragma unroll
    for (int k = 0; k < CK; k++)
        Qp[((size_t)blockIdx.y * CK + k) * CDn + d] = acc[k];
}
__global__ void q_reduce(const float* __restrict__ Qp, const float* __restrict__ bq,
                         float* __restrict__ Qout)
{
    int i = blockIdx.x * 256 + threadIdx.x;
    if (i >= CK * CDn) return;
    float s = bq[i % CDn];
#pragma unroll
    for (int y = 0; y < 8; y++) s += Qp[(size_t)y * CK * CDn + i];
    Qout[i] = s;
}

// ------- scores + masked softmax, 16 tokens per block -----------------------
#define SC_SMEM ((CK * CDn + 16 * CDn + 16 * CK) * 4)
__global__ void scores16(const float* __restrict__ Kt, const float* __restrict__ Q,
                         const int* __restrict__ mask, float* __restrict__ S)
{
    extern __shared__ float sm[];
    float* Qs  = sm;
    float* kts = Qs + CK * CDn;
    float* sk  = kts + 16 * CDn;
    int t0 = blockIdx.x * 16;
    int tid = threadIdx.x, lane = tid & 31, w = tid >> 5;

    for (int i = tid; i < CK * CDn; i += 256) Qs[i] = Q[i];
    for (int i = tid; i < 16 * CDn; i += 256) kts[i] = Kt[(size_t)t0 * CDn + i];
    __syncthreads();

#pragma unroll
    for (int tt = 2 * w; tt < 2 * w + 2; tt++) {
        const float* kr = kts + tt * CDn;
#pragma unroll
        for (int k = 0; k < CK; k++) {
            float acc = 0.f;
#pragma unroll
            for (int j = 0; j < CDn / 32; j++)
                acc += Qs[k * CDn + j * 32 + lane] * kr[j * 32 + lane];
#pragma unroll
            for (int off = 16; off; off >>= 1)
                acc += __shfl_xor_sync(0xffffffffu, acc, off);
            if (lane == 0) sk[tt * CK + k] = acc;
        }
    }
    __syncthreads();

    int tt = tid >> 4, k = tid & 15;
    int bn = t0 + tt;
    if (mask[bn] == 0) {
        S[(size_t)bn * CK + k] = 1.0f / CK;
    } else {
        const float scale = rsqrtf((float)(CDn / 8));
        float m = -INFINITY, ssum = 0.f;
#pragma unroll
        for (int j = 0; j < CK; j++) m = fmaxf(m, sk[tt * CK + j]);
#pragma unroll
        for (int j = 0; j < CK; j++) ssum += __expf((sk[tt * CK + j] - m) * scale);
        S[(size_t)bn * CK + k] = __expf((sk[tt * CK + k] - m) * scale) / ssum;
    }
}

// ------- V agg + fuse gate ---------------------------------------------------
__global__ void vagg_kernel(const float* __restrict__ S, const float* __restrict__ Vt,
                            const float* __restrict__ nq, const float* __restrict__ fg,
                            float* __restrict__ Vout)
{
    int b = blockIdx.y;
    int d0 = blockIdx.x * 128;
    __shared__ float Ss[CN * CK];
    __shared__ float vts[128];
    for (int i = threadIdx.x; i < CN * CK; i += 256)
        Ss[i] = S[(size_t)b * CN * CK + i];
    int k  = threadIdx.x >> 4;
    int ds = threadIdx.x & 15;
    float acc[8] = {};
    for (int n = 0; n < CN; n++) {
        __syncthreads();
        if (threadIdx.x < 128)
            vts[threadIdx.x] = Vt[((size_t)b * CN + n) * CDn + d0 + threadIdx.x];
        __syncthreads();
        float sv = Ss[n * CK + k];
#pragma unroll
        for (int c = 0; c < 8; c++) acc[c] += sv * vts[ds + 16 * c];
    }
    float g = 1.f / (1.f + __expf(-fg[0]));
#pragma unroll
    for (int c = 0; c < 8; c++) {
        int d = d0 + ds + 16 * c;
        Vout[((size_t)b * CK + k) * CDn + d] = (1.f - g) * acc[c] + g * nq[k * CDn + d];
    }
}

// ---------------- edge reduce on merged H [4096, 1024] ----------------------
#define LDH (2 * CHID)
template <bool DO_SOFTMAX>
__global__ void edge_kernel(const float* __restrict__ H,
                            const float* __restrict__ be1, const float* __restrict__ We2,
                            const float* __restrict__ be2, float* __restrict__ out)
{
    extern __shared__ float sm[];
    float* HIs  = sm;
    float* HJs  = HIs + CHID * CK;
    float* be1s = HJs + CHID * CK;
    float* we2s = be1s + CHID;
    float* Es   = we2s + CHID;
    int b = blockIdx.x;
    for (int idx = threadIdx.x; idx < CK * CHID; idx += 256) {
        int i = idx / CHID, h = idx % CHID;
        HIs[h * CK + i] = H[((size_t)b * CK + i) * LDH + h];
        HJs[h * CK + i] = H[((size_t)b * CK + i) * LDH + CHID + h];
    }
    for (int idx = threadIdx.x; idx < CHID; idx += 256) {
        be1s[idx] = be1[idx];
        we2s[idx] = We2[idx];
    }
    __syncthreads();
    int i = threadIdx.x >> 4, j = threadIdx.x & 15;
    float acc = be2[0];
#pragma unroll 4
    for (int h = 0; h < CHID; h++) {
        float v = HIs[h * CK + i] + HJs[h * CK + j] + be1s[h];
        acc += fmaxf(v, 0.f) * we2s[h];
    }
    if (!DO_SOFTMAX) {
        out[(size_t)b * CK * CK + i * CK + j] = acc;
    } else {
        Es[i * CK + j] = acc;
        __syncthreads();
        float m = -INFINITY;
#pragma unroll
        for (int jj = 0; jj < CK; jj++) m = fmaxf(m, Es[i * CK + jj]);
        float ssum = 0.f;
#pragma unroll
        for (int jj = 0; jj < CK; jj++) ssum += __expf(Es[i * CK + jj] - m);
        out[(size_t)b * CK * CK + i * CK + j] = __expf(acc - m) / ssum;
    }
}

// ------- GNN update -----------------------------------------------------------
__global__ void gnn_update(const float* __restrict__ A, const float* __restrict__ M,
                           float* __restrict__ V)
{
    int b = blockIdx.y;
    int d0 = blockIdx.x * 128;
    __shared__ float As[CK * CK];
    __shared__ float Ms[128];
    for (int idx = threadIdx.x; idx < CK * CK; idx += 256)
        As[idx] = A[(size_t)b * CK * CK + idx];
    int i  = threadIdx.x >> 4;
    int ds = threadIdx.x & 15;
    float acc[8] = {};
    for (int j = 0; j < CK; j++) {
        __syncthreads();
        if (threadIdx.x < 128)
            Ms[threadIdx.x] = M[((size_t)b * CK + j) * CDn + d0 + threadIdx.x];
        __syncthreads();
        float a = As[i * CK + j];
#pragma unroll
        for (int c = 0; c < 8; c++) acc[c] += a * Ms[ds + 16 * c];
    }
#pragma unroll
    for (int c = 0; c < 8; c++) {
        size_t o = ((size_t)b * CK + i) * CDn + d0 + ds + 16 * c;
        V[o] += fmaxf(acc[c], 0.f);
    }
}

// ---------------------------------------------------------------------------
extern "C" void kernel_launch(void* const* d_in, const int* in_sizes, int n_in,
                              void* d_out, int out_size)
{
    const float* w    = (const float*)d_in[0];
    const int*   mask = (const int*)  d_in[1];
    const float* nq   = (const float*)d_in[2];
    const float* Wq   = (const float*)d_in[3];
    const float* bq   = (const float*)d_in[4];
    const float* Wk   = (const float*)d_in[5];
    const float* bk   = (const float*)d_in[6];
    const float* Wv   = (const float*)d_in[7];
    const float* bv   = (const float*)d_in[8];
    const float* We1  = (const float*)d_in[9];
    const float* be1  = (const float*)d_in[10];
    const float* We2  = (const float*)d_in[11];
    const float* be2  = (const float*)d_in[12];
    const float* fg   = (const float*)d_in[13];
    const float* Wg   = (const float*)d_in[14];
    const float* bg   = (const float*)d_in[15];

    float* S = (float*)d_out;                       // [B,N,K]
    float* V = S + (size_t)CB * CN * CK;            // [B,K,Dn]
    float* E = V + (size_t)CB * CK * CDn;           // [B,K,K]

    float *Kt, *Vt, *Qb, *Qp, *Ab, *Hb, *Mg, *sa, *sv, *sw;
    int8_t *wq1, *wq2, *vq1, *vq2, *Wq1, *Wq2;
    cudaGetSymbolAddress((void**)&Kt, g_Kt);
    cudaGetSymbolAddress((void**)&Vt, g_Vt);
    cudaGetSymbolAddress((void**)&Qb, g_Q);
    cudaGetSymbolAddress((void**)&Qp, g_Qp);
    cudaGetSymbolAddress((void**)&Ab, g_A);
    cudaGetSymbolAddress((void**)&Hb, g_H);
    cudaGetSymbolAddress((void**)&Mg, g_Mg);
    cudaGetSymbolAddress((void**)&wq1, g_wq1);
    cudaGetSymbolAddress((void**)&wq2, g_wq2);
    cudaGetSymbolAddress((void**)&sa,  g_sa);
    cudaGetSymbolAddress((void**)&vq1, g_vq1);
    cudaGetSymbolAddress((void**)&vq2, g_vq2);
    cudaGetSymbolAddress((void**)&sv,  g_sv);
    cudaGetSymbolAddress((void**)&Wq1, g_Wq1);
    cudaGetSymbolAddress((void**)&Wq2, g_Wq2);
    cudaGetSymbolAddress((void**)&sw,  g_sw);

    const int EDGE_SMEM = (2 * CHID * CK + 2 * CHID + CK * CK) * (int)sizeof(float);
    cudaFuncSetAttribute(edge_kernel<true>,  cudaFuncAttributeMaxDynamicSharedMemorySize, EDGE_SMEM);
    cudaFuncSetAttribute(edge_kernel<false>, cudaFuncAttributeMaxDynamicSharedMemorySize, EDGE_SMEM);
    cudaFuncSetAttribute(gemm_i8, cudaFuncAttributeMaxDynamicSharedMemorySize, GSMEM);
    cudaFuncSetAttribute(scores16, cudaFuncAttributeMaxDynamicSharedMemorySize, SC_SMEM);

    const int Mtok = CB * CN;   // 19712
    const int Mkv  = CB * CK;   // 4096

    // 1. quantize w (per-row 2-limb int8)
    aquant<<<Mtok, 256>>>(w, wq1, wq2, sa);
    // 2. quantize all weights (transposed, per-output-channel)
    wquant<<<dim3(24, 6), 256>>>(Wk, Wv, We1, Wg, Wq1, Wq2, sw);
    // 3. Q partial (batch-invariant)
    q_partial<<<dim3(CDn / 128, 8), 128>>>(nq, Wq, Qp);
    // 4. Kt projection  <-- ncu profiles launch #4
    gemm_i8<<<dim3(CDn / 128, Mtok / 128), 256, GSMEM>>>(wq1, wq2, sa, Wq1, Wq2, sw, bk, Kt, CDn);
    // 5. Q reduce
    q_reduce<<<(CK * CDn + 255) / 256, 256>>>(Qp, bq, Qb);
    // 6. Vt projection
    gemm_i8<<<dim3(CDn / 128, Mtok / 128), 256, GSMEM>>>(wq1, wq2, sa,
                                                         Wq1 + (size_t)768 * GK, Wq2 + (size_t)768 * GK,
                                                         sw + 768, bv, Vt, CDn);
    // 7. scores + masked softmax
    scores16<<<Mtok / 16, 256, SC_SMEM>>>(Kt, Qb, mask, S);
    // 8. V aggregation + gate
    vagg_kernel<<<dim3(CDn / 128, CB), 256>>>(S, Vt, nq, fg, V);
    // 9. quantize V
    aquant<<<Mkv, 256>>>(V, vq1, vq2, sv);

    // 10-11. pre-GNN edge logits (merged Hi|Hj GEMM) -> A = softmax(E)
    gemm_i8<<<dim3(2 * CHID / 128, Mkv / 128), 256, GSMEM>>>(vq1, vq2, sv,
                                                             Wq1 + (size_t)1536 * GK, Wq2 + (size_t)1536 * GK,
                                                             sw + 1536, nullptr, Hb, LDH);
    edge_kernel<true><<<CB, 256, EDGE_SMEM>>>(Hb, be1, We2, be2, Ab);

    // 12-17. GNN layers
    for (int l = 0; l < CL; l++) {
        gemm_i8<<<dim3(CDn / 128, Mkv / 128), 256, GSMEM>>>(
            vq1, vq2, sv,
            Wq1 + (size_t)(2560 + 768 * l) * GK, Wq2 + (size_t)(2560 + 768 * l) * GK,
            sw + 2560 + 768 * l, bg + (size_t)l * CDn, Mg, CDn);
        gnn_update<<<dim3(CDn / 128, CB), 256>>>(Ab, Mg, V);
        aquant<<<Mkv, 256>>>(V, vq1, vq2, sv);
    }

    // 18-19. post-GNN edge logits -> E (output)
    gemm_i8<<<dim3(2 * CHID / 128, Mkv / 128), 256, GSMEM>>>(vq1, vq2, sv,
                                                             Wq1 + (size_t)1536 * GK, Wq2 + (size_t)1536 * GK,
                                                             sw + 1536, nullptr, Hb, LDH);
    edge_kernel<false><<<CB, 256, EDGE_SMEM>>>(Hb, be1, We2, be2, E);
}

// round 6
// speedup vs baseline: 5.2028x; 5.2028x over previous
#include <cuda_runtime.h>
#include <cuda_bf16.h>
#include <math.h>
#include <stdint.h>

#define CB   256   // batch
#define CN   77    // tokens
#define CD   768   // token dim
#define CK   16    // nodes
#define CDn  768   // node dim
#define CHID 512   // edge hidden
#define CL   2     // gnn layers

#define GK     768          // shared inner dim of all tensor GEMMs
#define KCH    64           // bf16 K elems per chunk (128B rows)
#define NCHUNK (GK / KCH)   // 12
#define TILEB  16384        // one 128x64 bf16 tile in smem
#define BUFB   (4 * TILEB)  // Ah, Al, Bh, Bl
#define NSTAGE 3
#define GSMEM  (NSTAGE * BUFB)  // 196608

// ---------------- scratch (device globals; no allocation allowed) ----------
__device__ float g_Q  [CK * CDn];
__device__ float g_Qp [8 * CK * CDn];
__device__ float g_QKT[CK * CD];        // QK[k, d] = sum_dn Q[k,dn] * Wk[d,dn]
__device__ float g_off[CK];             // off[k] = Q[k,:] . bk
__device__ float g_sumS[CB * CK];       // sum_n S[b,n,k]
__device__ float g_A [CB * CK * CK];
__device__ float g_H [CB * CK * 2 * CHID];   // [4096, 1024]: Hi | Hj
__device__ float g_Mg[CB * CK * CDn];        // GEMM outputs (Cv, then gnn msgs)
__device__ __nv_bfloat16 g_uh[CB * CK * CDn];
__device__ __nv_bfloat16 g_ul[CB * CK * CDn];
__device__ __nv_bfloat16 g_vh[CB * CK * CDn];
__device__ __nv_bfloat16 g_vl[CB * CK * CDn];
// transposed weights [3328, 768]: Wv(0) We1a(768) We1b(1280) Wg0(1792) Wg1(2560)
__device__ __nv_bfloat16 g_Wth[3328 * GK];
__device__ __nv_bfloat16 g_Wtl[3328 * GK];

// ---------------- PTX helpers ----------------------------------------------
__device__ __forceinline__ uint32_t smem_u32(const void* p) {
    uint32_t a;
    asm("{ .reg .u64 t; cvta.to.shared.u64 t, %1; cvt.u32.u64 %0, t; }" : "=r"(a) : "l"(p));
    return a;
}
__device__ __forceinline__ void cpa16(uint32_t sa, const void* ga) {
    asm volatile("cp.async.cg.shared.global [%0], [%1], 16;" :: "r"(sa), "l"(ga));
}
__device__ __forceinline__ void ldsm4(uint32_t* r, uint32_t addr) {
    asm volatile("ldmatrix.sync.aligned.m8n8.x4.shared.b16 {%0,%1,%2,%3}, [%4];"
                 : "=r"(r[0]), "=r"(r[1]), "=r"(r[2]), "=r"(r[3]) : "r"(addr));
}
__device__ __forceinline__ void mma16816(float* c, const uint32_t* a, uint32_t b0, uint32_t b1) {
    asm volatile(
        "mma.sync.aligned.m16n8k16.row.col.f32.bf16.bf16.f32 "
        "{%0,%1,%2,%3}, {%4,%5,%6,%7}, {%8,%9}, {%0,%1,%2,%3};"
        : "+f"(c[0]), "+f"(c[1]), "+f"(c[2]), "+f"(c[3])
        : "r"(a[0]), "r"(a[1]), "r"(a[2]), "r"(a[3]), "r"(b0), "r"(b1));
}
__device__ __forceinline__ void split_bf16(float x, __nv_bfloat16& h, __nv_bfloat16& l) {
    h = __float2bfloat16(x);
    l = __float2bfloat16(x - __bfloat162float(h));
}

// ---------------- Q = nq @ Wq + bq: partial over e-ranges, then reduce -----
__global__ void q_partial(const float* __restrict__ nq, const float* __restrict__ Wq,
                          float* __restrict__ Qp)
{
    int d = blockIdx.x * 128 + threadIdx.x;
    int e0 = blockIdx.y * 96;
    float acc[CK] = {};
    for (int e = e0; e < e0 + 96; e++) {
        float wv = Wq[(size_t)e * CDn + d];
#pragma unroll
        for (int k = 0; k < CK; k++) acc[k] += nq[k * CDn + e] * wv;
    }
#pragma unroll
    for (int k = 0; k < CK; k++)
        Qp[((size_t)blockIdx.y * CK + k) * CDn + d] = acc[k];
}
__global__ void q_reduce(const float* __restrict__ Qp, const float* __restrict__ bq,
                         float* __restrict__ Qout)
{
    int i = blockIdx.x * 256 + threadIdx.x;
    if (i >= CK * CDn) return;
    float s = bq[i % CDn];
#pragma unroll
    for (int y = 0; y < 8; y++) s += Qp[(size_t)y * CK * CDn + i];
    Qout[i] = s;
}

// ------- QK[k,d] = Q[k,:] . Wk[d,:]; block 768 computes off[k] = Q[k,:].bk --
__global__ void qk_kernel(const float* __restrict__ Q, const float* __restrict__ Wk,
                          const float* __restrict__ bk,
                          float* __restrict__ QKT, float* __restrict__ off)
{
    __shared__ float row[CDn];
    int d = blockIdx.x;
    const float* src = (d == CD) ? bk : Wk + (size_t)d * CDn;
    int tid = threadIdx.x, lane = tid & 31, w = tid >> 5;
    for (int i = tid; i < CDn; i += 256) row[i] = src[i];
    __syncthreads();
#pragma unroll
    for (int k = 2 * w; k < 2 * w + 2; k++) {
        float acc = 0.f;
#pragma unroll
        for (int j = 0; j < CDn / 32; j++)
            acc += Q[k * CDn + j * 32 + lane] * row[j * 32 + lane];
#pragma unroll
        for (int o = 16; o; o >>= 1)
            acc += __shfl_xor_sync(0xffffffffu, acc, o);
        if (lane == 0) {
            if (d == CD) off[k] = acc;
            else         QKT[k * CD + d] = acc;
        }
    }
}

// ------- fused scores+softmax: s[b,n,k] = w[b,n,:].QK[k,:] + off[k] ---------
#define SC_SMEM ((CK * CD + 16 * CD + 16 * CK + CK) * 4)
__global__ void scores_fused(const float* __restrict__ w, const float* __restrict__ QKT,
                             const float* __restrict__ off, const int* __restrict__ mask,
                             float* __restrict__ S)
{
    extern __shared__ float sm[];
    float* Qs  = sm;                 // [16][768] QK
    float* ws  = Qs + CK * CD;       // [16 tokens][768]
    float* sk  = ws + 16 * CD;       // [16 tokens][16]
    float* offs = sk + 16 * CK;      // [16]
    int t0 = blockIdx.x * 16;
    int tid = threadIdx.x, lane = tid & 31, wd = tid >> 5;

    for (int i = tid; i < CK * CD; i += 256) Qs[i] = QKT[i];
    for (int i = tid; i < 16 * CD; i += 256) ws[i] = w[(size_t)t0 * CD + i];
    if (tid < CK) offs[tid] = off[tid];
    __syncthreads();

#pragma unroll
    for (int tt = 2 * wd; tt < 2 * wd + 2; tt++) {
        const float* wr = ws + tt * CD;
#pragma unroll
        for (int k = 0; k < CK; k++) {
            float acc = 0.f;
#pragma unroll
            for (int j = 0; j < CD / 32; j++)
                acc += Qs[k * CD + j * 32 + lane] * wr[j * 32 + lane];
#pragma unroll
            for (int o = 16; o; o >>= 1)
                acc += __shfl_xor_sync(0xffffffffu, acc, o);
            if (lane == 0) sk[tt * CK + k] = acc + offs[k];
        }
    }
    __syncthreads();

    int tt = tid >> 4, k = tid & 15;
    int bn = t0 + tt;
    if (mask[bn] == 0) {
        S[(size_t)bn * CK + k] = 1.0f / CK;
    } else {
        const float scale = rsqrtf((float)(CDn / 8));
        float m = -INFINITY, ssum = 0.f;
#pragma unroll
        for (int j = 0; j < CK; j++) m = fmaxf(m, sk[tt * CK + j]);
#pragma unroll
        for (int j = 0; j < CK; j++) ssum += __expf((sk[tt * CK + j] - m) * scale);
        S[(size_t)bn * CK + k] = __expf((sk[tt * CK + k] - m) * scale) / ssum;
    }
}

// ------- U[b,k,:] = sum_n S[b,n,k] * w[b,n,:]  (+ sumS); write bf16 limbs ---
__global__ void uagg_kernel(const float* __restrict__ S, const float* __restrict__ w,
                            __nv_bfloat16* __restrict__ uh, __nv_bfloat16* __restrict__ ul,
                            float* __restrict__ sumS)
{
    int b = blockIdx.y;
    int d0 = blockIdx.x * 128;
    __shared__ float Ss[CN * CK];
    __shared__ float ws[128];
    for (int i = threadIdx.x; i < CN * CK; i += 256)
        Ss[i] = S[(size_t)b * CN * CK + i];
    int k  = threadIdx.x >> 4;
    int ds = threadIdx.x & 15;
    float acc[8] = {};
    float ssum = 0.f;
    for (int n = 0; n < CN; n++) {
        __syncthreads();
        if (threadIdx.x < 128)
            ws[threadIdx.x] = w[((size_t)b * CN + n) * CD + d0 + threadIdx.x];
        __syncthreads();
        float sv = Ss[n * CK + k];
        ssum += sv;
#pragma unroll
        for (int c = 0; c < 8; c++) acc[c] += sv * ws[ds + 16 * c];
    }
#pragma unroll
    for (int c = 0; c < 8; c++) {
        size_t o = ((size_t)b * CK + k) * CDn + d0 + ds + 16 * c;
        __nv_bfloat16 h, l;
        split_bf16(acc[c], h, l);
        uh[o] = h; ul[o] = l;
    }
    if (blockIdx.x == 0 && ds == 0) sumS[b * CK + k] = ssum;
}

// ------- all 5 weight matrices transposed + split to bf16 limbs -------------
__global__ void split_weights(const float* __restrict__ Wv, const float* __restrict__ We1,
                              const float* __restrict__ Wg,
                              __nv_bfloat16* __restrict__ dh, __nv_bfloat16* __restrict__ dl) {
    int z = blockIdx.z;
    const float* src; int ld, ncols, dsto;
    switch (z) {
        case 0: src = Wv;                        ld = 768; ncols = 768; dsto = 0;    break;
        case 1: src = We1;                       ld = 512; ncols = 512; dsto = 768;  break;
        case 2: src = We1 + (size_t)768 * 512;   ld = 512; ncols = 512; dsto = 1280; break;
        case 3: src = Wg;                        ld = 768; ncols = 768; dsto = 1792; break;
        default: src = Wg + (size_t)768 * 768;   ld = 768; ncols = 768; dsto = 2560; break;
    }
    int n0 = blockIdx.x * 32, k0 = blockIdx.y * 32;
    if (n0 >= ncols) return;
    __shared__ float t[32][33];
    int tx = threadIdx.x, ty = threadIdx.y;
#pragma unroll
    for (int j = 0; j < 4; j++)
        t[ty + 8 * j][tx] = src[(size_t)(k0 + ty + 8 * j) * ld + n0 + tx];
    __syncthreads();
#pragma unroll
    for (int j = 0; j < 4; j++) {
        float x = t[tx][ty + 8 * j];
        __nv_bfloat16 h, l;
        split_bf16(x, h, l);
        size_t o = (size_t)(dsto + n0 + ty + 8 * j) * GK + k0 + tx;
        dh[o] = h;
        dl[o] = l;
    }
}

// ---------------- mma.sync split-bf16 GEMM, 3-stage cp.async pipeline --------
__global__ void __launch_bounds__(256, 1) gemm_mma(
    const __nv_bfloat16* __restrict__ Ah, const __nv_bfloat16* __restrict__ Al,
    const __nv_bfloat16* __restrict__ Bh, const __nv_bfloat16* __restrict__ Bl,
    const float* __restrict__ bias, float* __restrict__ C, int Nn)
{
    extern __shared__ char smem[];
    const uint32_t sbase = smem_u32(smem);
    const int tid = threadIdx.x;
    const int lane = tid & 31, wid = tid >> 5;
    const int warp_m = wid >> 2, warp_n = wid & 3;   // 2 x 4 warp grid
    const int row0 = blockIdx.y * 128;
    const int col0 = blockIdx.x * 128;

    float acc[4][4][4];
#pragma unroll
    for (int a = 0; a < 4; a++)
#pragma unroll
        for (int b = 0; b < 4; b++)
#pragma unroll
            for (int c = 0; c < 4; c++) acc[a][b][c] = 0.f;

#define ISSUE_CHUNK(chunk, buf)                                                     \
    do {                                                                            \
        uint32_t bufo_ = sbase + (buf) * BUFB;                                      \
        _Pragma("unroll")                                                           \
        for (int it = 0; it < 16; it++) {                                           \
            int idx_ = it * 256 + tid;                                              \
            int t_ = idx_ >> 10;                                                    \
            int r_ = (idx_ >> 3) & 127;                                             \
            int c_ = idx_ & 7;                                                      \
            const __nv_bfloat16* sp_ =                                              \
                (t_ == 0) ? Ah + (size_t)(row0 + r_) * GK :                         \
                (t_ == 1) ? Al + (size_t)(row0 + r_) * GK :                         \
                (t_ == 2) ? Bh + (size_t)(col0 + r_) * GK :                         \
                            Bl + (size_t)(col0 + r_) * GK;                          \
            sp_ += (chunk) * KCH + c_ * 8;                                          \
            uint32_t sa_ = bufo_ + t_ * TILEB + r_ * 128 + ((c_ ^ (r_ & 7)) << 4);  \
            cpa16(sa_, sp_);                                                        \
        }                                                                           \
        asm volatile("cp.async.commit_group;" ::: "memory");                        \
    } while (0)

    ISSUE_CHUNK(0, 0);
    ISSUE_CHUNK(1, 1);

    const int rA  = warp_m * 64 + (lane & 15);
    const int khA = lane >> 4;
    const int rB  = warp_n * 32 + (lane & 7) + ((lane >> 4) << 3);
    const int khB = (lane >> 3) & 1;
    const int swA = rA & 7, swB = rB & 7;

    for (int i = 0; i < NCHUNK; i++) {
        if (i + 2 < NCHUNK) {
            ISSUE_CHUNK(i + 2, (i + 2) % NSTAGE);
            asm volatile("cp.async.wait_group 2;" ::: "memory");
        } else if (i + 1 < NCHUNK) {
            asm volatile("cp.async.wait_group 1;" ::: "memory");
        } else {
            asm volatile("cp.async.wait_group 0;" ::: "memory");
        }
        __syncthreads();
        uint32_t bufo = sbase + (i % NSTAGE) * BUFB;
#pragma unroll
        for (int kk = 0; kk < 4; kk++) {
            uint32_t a[2][4][4];
            uint32_t b[2][2][4];
            int ckA = kk * 2 + khA;
            int ckB = kk * 2 + khB;
#pragma unroll
            for (int mt = 0; mt < 4; mt++) {
                uint32_t ad = bufo + (rA + mt * 16) * 128 + (((ckA ^ swA)) << 4);
                ldsm4(a[0][mt], ad);
                ldsm4(a[1][mt], ad + TILEB);
            }
#pragma unroll
            for (int nt = 0; nt < 2; nt++) {
                uint32_t bd = bufo + 2 * TILEB + (rB + nt * 16) * 128 + (((ckB ^ swB)) << 4);
                ldsm4(b[0][nt], bd);
                ldsm4(b[1][nt], bd + TILEB);
            }
#pragma unroll
            for (int mt = 0; mt < 4; mt++)
#pragma unroll
                for (int ng = 0; ng < 4; ng++) {
                    uint32_t b0h = b[0][ng >> 1][(ng & 1) * 2 + 0];
                    uint32_t b1h = b[0][ng >> 1][(ng & 1) * 2 + 1];
                    uint32_t b0l = b[1][ng >> 1][(ng & 1) * 2 + 0];
                    uint32_t b1l = b[1][ng >> 1][(ng & 1) * 2 + 1];
                    mma16816(acc[mt][ng], a[0][mt], b0h, b1h);   // Ah*Bh
                    mma16816(acc[mt][ng], a[0][mt], b0l, b1l);   // Ah*Bl
                    mma16816(acc[mt][ng], a[1][mt], b0h, b1h);   // Al*Bh
                }
        }
        __syncthreads();
    }

    const int rowE = row0 + warp_m * 64 + (lane >> 2);
#pragma unroll
    for (int mt = 0; mt < 4; mt++) {
#pragma unroll
        for (int ng = 0; ng < 4; ng++) {
            int col = col0 + warp_n * 32 + ng * 8 + 2 * (lane & 3);
            float b0 = bias ? bias[col + 0] : 0.f;
            float b1 = bias ? bias[col + 1] : 0.f;
            float2 v0 = make_float2(acc[mt][ng][0] + b0, acc[mt][ng][1] + b1);
            float2 v1 = make_float2(acc[mt][ng][2] + b0, acc[mt][ng][3] + b1);
            *(float2*)(C + (size_t)(rowE + mt * 16) * Nn + col) = v0;
            *(float2*)(C + (size_t)(rowE + mt * 16 + 8) * Nn + col) = v1;
        }
    }
#undef ISSUE_CHUNK
}

// ------- V = (1-g)*(Cv + sumS*bv) + g*nq; write fp32 V + bf16 limbs ---------
__global__ void gate_split(const float* __restrict__ Cv, const float* __restrict__ sumS,
                           const float* __restrict__ bv, const float* __restrict__ nq,
                           const float* __restrict__ fg, float* __restrict__ V,
                           __nv_bfloat16* __restrict__ vh, __nv_bfloat16* __restrict__ vl)
{
    int i4 = blockIdx.x * 256 + threadIdx.x;
    if (i4 >= CB * CK * CDn / 4) return;
    int base = i4 * 4;
    int row = base / CDn;
    int col = base % CDn;
    int k = row & 15;
    float g = 1.f / (1.f + __expf(-fg[0]));
    float ss = sumS[row];
    float4 c = ((const float4*)Cv)[i4];
    float4 b = *(const float4*)(bv + col);
    float4 q = *(const float4*)(nq + k * CDn + col);
    float4 v;
    v.x = (1.f - g) * (c.x + ss * b.x) + g * q.x;
    v.y = (1.f - g) * (c.y + ss * b.y) + g * q.y;
    v.z = (1.f - g) * (c.z + ss * b.z) + g * q.z;
    v.w = (1.f - g) * (c.w + ss * b.w) + g * q.w;
    ((float4*)V)[i4] = v;
    __nv_bfloat16 h0, h1, h2, h3, l0, l1, l2, l3;
    split_bf16(v.x, h0, l0); split_bf16(v.y, h1, l1);
    split_bf16(v.z, h2, l2); split_bf16(v.w, h3, l3);
    ((__nv_bfloat162*)vh)[2 * i4 + 0] = __nv_bfloat162(h0, h1);
    ((__nv_bfloat162*)vh)[2 * i4 + 1] = __nv_bfloat162(h2, h3);
    ((__nv_bfloat162*)vl)[2 * i4 + 0] = __nv_bfloat162(l0, l1);
    ((__nv_bfloat162*)vl)[2 * i4 + 1] = __nv_bfloat162(l2, l3);
}

// ---------------- edge reduce on merged H [4096, 1024] ----------------------
#define LDH (2 * CHID)
template <bool DO_SOFTMAX>
__global__ void edge_kernel(const float* __restrict__ H,
                            const float* __restrict__ be1, const float* __restrict__ We2,
                            const float* __restrict__ be2, float* __restrict__ out)
{
    extern __shared__ float sm[];
    float* HIs  = sm;
    float* HJs  = HIs + CHID * CK;
    float* be1s = HJs + CHID * CK;
    float* we2s = be1s + CHID;
    float* Es   = we2s + CHID;
    int b = blockIdx.x;
    for (int idx = threadIdx.x; idx < CK * CHID; idx += 256) {
        int i = idx / CHID, h = idx % CHID;
        HIs[h * CK + i] = H[((size_t)b * CK + i) * LDH + h];
        HJs[h * CK + i] = H[((size_t)b * CK + i) * LDH + CHID + h];
    }
    for (int idx = threadIdx.x; idx < CHID; idx += 256) {
        be1s[idx] = be1[idx];
        we2s[idx] = We2[idx];
    }
    __syncthreads();
    int i = threadIdx.x >> 4, j = threadIdx.x & 15;
    float acc = be2[0];
#pragma unroll 4
    for (int h = 0; h < CHID; h++) {
        float v = HIs[h * CK + i] + HJs[h * CK + j] + be1s[h];
        acc += fmaxf(v, 0.f) * we2s[h];
    }
    if (!DO_SOFTMAX) {
        out[(size_t)b * CK * CK + i * CK + j] = acc;
    } else {
        Es[i * CK + j] = acc;
        __syncthreads();
        float m = -INFINITY;
#pragma unroll
        for (int jj = 0; jj < CK; jj++) m = fmaxf(m, Es[i * CK + jj]);
        float ssum = 0.f;
#pragma unroll
        for (int jj = 0; jj < CK; jj++) ssum += __expf(Es[i * CK + jj] - m);
        out[(size_t)b * CK * CK + i * CK + j] = __expf(acc - m) / ssum;
    }
}

// ------- GNN update + bf16 split ---------------------------------------------
__global__ void gnn_update(const float* __restrict__ A, const float* __restrict__ M,
                           float* __restrict__ V,
                           __nv_bfloat16* __restrict__ vh, __nv_bfloat16* __restrict__ vl)
{
    int b = blockIdx.y;
    int d0 = blockIdx.x * 128;
    __shared__ float As[CK * CK];
    __shared__ float Ms[128];
    for (int idx = threadIdx.x; idx < CK * CK; idx += 256)
        As[idx] = A[(size_t)b * CK * CK + idx];
    int i  = threadIdx.x >> 4;
    int ds = threadIdx.x & 15;
    float acc[8] = {};
    for (int j = 0; j < CK; j++) {
        __syncthreads();
        if (threadIdx.x < 128)
            Ms[threadIdx.x] = M[((size_t)b * CK + j) * CDn + d0 + threadIdx.x];
        __syncthreads();
        float a = As[i * CK + j];
#pragma unroll
        for (int c = 0; c < 8; c++) acc[c] += a * Ms[ds + 16 * c];
    }
#pragma unroll
    for (int c = 0; c < 8; c++) {
        size_t o = ((size_t)b * CK + i) * CDn + d0 + ds + 16 * c;
        float v = V[o] + fmaxf(acc[c], 0.f);
        V[o] = v;
        __nv_bfloat16 h, l;
        split_bf16(v, h, l);
        vh[o] = h; vl[o] = l;
    }
}

// ---------------------------------------------------------------------------
extern "C" void kernel_launch(void* const* d_in, const int* in_sizes, int n_in,
                              void* d_out, int out_size)
{
    const float* w    = (const float*)d_in[0];
    const int*   mask = (const int*)  d_in[1];
    const float* nq   = (const float*)d_in[2];
    const float* Wq   = (const float*)d_in[3];
    const float* bq   = (const float*)d_in[4];
    const float* Wk   = (const float*)d_in[5];
    const float* bk   = (const float*)d_in[6];
    const float* Wv   = (const float*)d_in[7];
    const float* bv   = (const float*)d_in[8];
    const float* We1  = (const float*)d_in[9];
    const float* be1  = (const float*)d_in[10];
    const float* We2  = (const float*)d_in[11];
    const float* be2  = (const float*)d_in[12];
    const float* fg   = (const float*)d_in[13];
    const float* Wg   = (const float*)d_in[14];
    const float* bg   = (const float*)d_in[15];

    float* S = (float*)d_out;                       // [B,N,K]
    float* V = S + (size_t)CB * CN * CK;            // [B,K,Dn]
    float* E = V + (size_t)CB * CK * CDn;           // [B,K,K]

    float *Qb, *Qp, *QKT, *off, *sumS, *Ab, *Hb, *Mg;
    __nv_bfloat16 *uh, *ul, *vh, *vl, *Wth, *Wtl;
    cudaGetSymbolAddress((void**)&Qb,  g_Q);
    cudaGetSymbolAddress((void**)&Qp,  g_Qp);
    cudaGetSymbolAddress((void**)&QKT, g_QKT);
    cudaGetSymbolAddress((void**)&off, g_off);
    cudaGetSymbolAddress((void**)&sumS, g_sumS);
    cudaGetSymbolAddress((void**)&Ab,  g_A);
    cudaGetSymbolAddress((void**)&Hb,  g_H);
    cudaGetSymbolAddress((void**)&Mg,  g_Mg);
    cudaGetSymbolAddress((void**)&uh,  g_uh);
    cudaGetSymbolAddress((void**)&ul,  g_ul);
    cudaGetSymbolAddress((void**)&vh,  g_vh);
    cudaGetSymbolAddress((void**)&vl,  g_vl);
    cudaGetSymbolAddress((void**)&Wth, g_Wth);
    cudaGetSymbolAddress((void**)&Wtl, g_Wtl);

    const int EDGE_SMEM = (2 * CHID * CK + 2 * CHID + CK * CK) * (int)sizeof(float);
    cudaFuncSetAttribute(edge_kernel<true>,  cudaFuncAttributeMaxDynamicSharedMemorySize, EDGE_SMEM);
    cudaFuncSetAttribute(edge_kernel<false>, cudaFuncAttributeMaxDynamicSharedMemorySize, EDGE_SMEM);
    cudaFuncSetAttribute(gemm_mma, cudaFuncAttributeMaxDynamicSharedMemorySize, GSMEM);
    cudaFuncSetAttribute(scores_fused, cudaFuncAttributeMaxDynamicSharedMemorySize, SC_SMEM);

    const int Mtok = CB * CN;   // 19712
    const int Mkv  = CB * CK;   // 4096
    dim3 tb(32, 8);

    // 1-2. Q = nq @ Wq + bq (batch-invariant)
    q_partial<<<dim3(CDn / 128, 8), 128>>>(nq, Wq, Qp);
    q_reduce<<<(CK * CDn + 255) / 256, 256>>>(Qp, bq, Qb);
    // 3. QK = Q @ Wk^T, off = Q @ bk
    qk_kernel<<<CD + 1, 256>>>(Qb, Wk, bk, QKT, off);
    // 4. fused scores + masked softmax  <-- profiled launch
    scores_fused<<<Mtok / 16, 256, SC_SMEM>>>(w, QKT, off, mask, S);
    // 5. U = S^T w (per batch) + sumS, split to bf16 limbs
    uagg_kernel<<<dim3(CDn / 128, CB), 256>>>(S, w, uh, ul, sumS);
    // 6. weight transpose+split (independent; placed late to overlap nothing critical)
    split_weights<<<dim3(24, 24, 5), tb>>>(Wv, We1, Wg, Wth, Wtl);
    // 7. Cv = U @ Wv   (no bias; bias folded in gate_split with sumS)
    gemm_mma<<<dim3(CDn / 128, Mkv / 128), 256, GSMEM>>>(uh, ul, Wth, Wtl, nullptr, Mg, CDn);
    // 8. V = (1-g)(Cv + sumS*bv) + g*nq; split
    gate_split<<<(Mkv * CDn / 4 + 255) / 256, 256>>>(Mg, sumS, bv, nq, fg, V, vh, vl);

    // 9-10. pre-GNN edge logits (merged Hi|Hj GEMM) -> A = softmax(E)
    gemm_mma<<<dim3(2 * CHID / 128, Mkv / 128), 256, GSMEM>>>(vh, vl, Wth + (size_t)768 * GK,
                                                              Wtl + (size_t)768 * GK, nullptr, Hb, LDH);
    edge_kernel<true><<<CB, 256, EDGE_SMEM>>>(Hb, be1, We2, be2, Ab);

    // 11-14. GNN layers
    for (int l = 0; l < CL; l++) {
        gemm_mma<<<dim3(CDn / 128, Mkv / 128), 256, GSMEM>>>(
            vh, vl, Wth + (size_t)(1792 + 768 * l) * GK, Wtl + (size_t)(1792 + 768 * l) * GK,
            bg + (size_t)l * CDn, Mg, CDn);
        gnn_update<<<dim3(CDn / 128, CB), 256>>>(Ab, Mg, V, vh, vl);
    }

    // 15-16. post-GNN edge logits -> E (output)
    gemm_mma<<<dim3(2 * CHID / 128, Mkv / 128), 256, GSMEM>>>(vh, vl, Wth + (size_t)768 * GK,
                                                              Wtl + (size_t)768 * GK, nullptr, Hb, LDH);
    edge_kernel<false><<<CB, 256, EDGE_SMEM>>>(Hb, be1, We2, be2, E);
}

// round 7
// speedup vs baseline: 7.0093x; 1.3472x over previous
#include <cuda_runtime.h>
#include <cuda_bf16.h>
#include <math.h>
#include <stdint.h>

#define CB   256   // batch
#define CN   77    // tokens
#define CD   768   // token dim
#define CK   16    // nodes
#define CDn  768   // node dim
#define CHID 512   // edge hidden
#define CL   2     // gnn layers

#define GK     768          // shared inner dim of all tensor GEMMs
#define KCH    64           // bf16 K elems per chunk (128B rows)
#define NCHUNK (GK / KCH)   // 12
#define TILEB  8192         // one 64x64 bf16 tile in smem (64 rows x 128B)
#define BUFB   (4 * TILEB)  // Ah, Al, Bh, Bl = 32 KB
#define NSTAGE 3
#define GSMEM  (NSTAGE * BUFB)  // 98304 -> 2 CTAs/SM

// ---------------- scratch (device globals; no allocation allowed) ----------
__device__ float g_Q  [CK * CDn];
__device__ float g_Qp [8 * CK * CDn];
__device__ float g_QKTt[CD * CK];       // QKT^T: [d][k]
__device__ float g_off[CK];             // off[k] = Q[k,:] . bk
__device__ float g_sumS[CB * CK];       // sum_n S[b,n,k]
__device__ float g_A [CB * CK * CK];
__device__ float g_H [CB * CK * 2 * CHID];   // [4096, 1024]: Hi | Hj
__device__ float g_Mg[CB * CK * CDn];        // GEMM outputs (Cv, then gnn msgs)
__device__ __nv_bfloat16 g_uh[CB * CK * CDn];
__device__ __nv_bfloat16 g_ul[CB * CK * CDn];
__device__ __nv_bfloat16 g_vh[CB * CK * CDn];
__device__ __nv_bfloat16 g_vl[CB * CK * CDn];
// transposed weights [3328, 768]: Wv(0) We1a(768) We1b(1280) Wg0(1792) Wg1(2560)
__device__ __nv_bfloat16 g_Wth[3328 * GK];
__device__ __nv_bfloat16 g_Wtl[3328 * GK];

// ---------------- PTX helpers ----------------------------------------------
__device__ __forceinline__ uint32_t smem_u32(const void* p) {
    uint32_t a;
    asm("{ .reg .u64 t; cvta.to.shared.u64 t, %1; cvt.u32.u64 %0, t; }" : "=r"(a) : "l"(p));
    return a;
}
__device__ __forceinline__ void cpa16(uint32_t sa, const void* ga) {
    asm volatile("cp.async.cg.shared.global [%0], [%1], 16;" :: "r"(sa), "l"(ga));
}
__device__ __forceinline__ void ldsm4(uint32_t* r, uint32_t addr) {
    asm volatile("ldmatrix.sync.aligned.m8n8.x4.shared.b16 {%0,%1,%2,%3}, [%4];"
                 : "=r"(r[0]), "=r"(r[1]), "=r"(r[2]), "=r"(r[3]) : "r"(addr));
}
__device__ __forceinline__ void mma16816(float* c, const uint32_t* a, uint32_t b0, uint32_t b1) {
    asm volatile(
        "mma.sync.aligned.m16n8k16.row.col.f32.bf16.bf16.f32 "
        "{%0,%1,%2,%3}, {%4,%5,%6,%7}, {%8,%9}, {%0,%1,%2,%3};"
        : "+f"(c[0]), "+f"(c[1]), "+f"(c[2]), "+f"(c[3])
        : "r"(a[0]), "r"(a[1]), "r"(a[2]), "r"(a[3]), "r"(b0), "r"(b1));
}
__device__ __forceinline__ void split_bf16(float x, __nv_bfloat16& h, __nv_bfloat16& l) {
    h = __float2bfloat16(x);
    l = __float2bfloat16(x - __bfloat162float(h));
}

// ---------------- Q = nq @ Wq + bq: partial over e-ranges, then reduce -----
__global__ void q_partial(const float* __restrict__ nq, const float* __restrict__ Wq,
                          float* __restrict__ Qp)
{
    int d = blockIdx.x * 128 + threadIdx.x;
    int e0 = blockIdx.y * 96;
    float acc[CK] = {};
    for (int e = e0; e < e0 + 96; e++) {
        float wv = Wq[(size_t)e * CDn + d];
#pragma unroll
        for (int k = 0; k < CK; k++) acc[k] += nq[k * CDn + e] * wv;
    }
#pragma unroll
    for (int k = 0; k < CK; k++)
        Qp[((size_t)blockIdx.y * CK + k) * CDn + d] = acc[k];
}
__global__ void q_reduce(const float* __restrict__ Qp, const float* __restrict__ bq,
                         float* __restrict__ Qout)
{
    int i = blockIdx.x * 256 + threadIdx.x;
    if (i >= CK * CDn) return;
    float s = bq[i % CDn];
#pragma unroll
    for (int y = 0; y < 8; y++) s += Qp[(size_t)y * CK * CDn + i];
    Qout[i] = s;
}

// ------- QKTt[d][k] = Q[k,:] . Wk[d,:]; block 768 computes off[k] ----------
__global__ void qk_kernel(const float* __restrict__ Q, const float* __restrict__ Wk,
                          const float* __restrict__ bk,
                          float* __restrict__ QKTt, float* __restrict__ off)
{
    __shared__ float row[CDn];
    int d = blockIdx.x;
    const float* src = (d == CD) ? bk : Wk + (size_t)d * CDn;
    int tid = threadIdx.x, lane = tid & 31, w = tid >> 5;
    for (int i = tid; i < CDn; i += 256) row[i] = src[i];
    __syncthreads();
#pragma unroll
    for (int k = 2 * w; k < 2 * w + 2; k++) {
        float acc = 0.f;
#pragma unroll
        for (int j = 0; j < CDn / 32; j++)
            acc += Q[k * CDn + j * 32 + lane] * row[j * 32 + lane];
#pragma unroll
        for (int o = 16; o; o >>= 1)
            acc += __shfl_xor_sync(0xffffffffu, acc, o);
        if (lane == 0) {
            if (d == CD) off[k] = acc;
            else         QKTt[d * CK + k] = acc;
        }
    }
}

// ------- fast fused scores+softmax: 128 tokens/block, 2 threads/token ------
#define WSROW 68
#define WS0_OFF (CD * CK)                  // 12288 floats
#define WS1_OFF (WS0_OFF + 128 * WSROW)    // +8704
#define OFF_OFF (WS1_OFF + 128 * WSROW)    // +8704
#define SCF_SMEM ((OFF_OFF + CK) * 4)      // 118848 bytes
__global__ void __launch_bounds__(256, 1) scores_fast(
    const float* __restrict__ w, const float* __restrict__ QKTt,
    const float* __restrict__ off, const int* __restrict__ mask,
    float* __restrict__ S)
{
    extern __shared__ float sm[];
    const uint32_t sbase = smem_u32(sm);
    int tid = threadIdx.x;
    int t0 = blockIdx.x * 128;

    // stage QKT^T [768][16] + off
    for (int i = tid; i < CD * CK / 4; i += 256)
        ((float4*)sm)[i] = ((const float4*)QKTt)[i];
    if (tid < CK) sm[OFF_OFF + tid] = off[tid];

#define SCF_ISSUE(chunk, wsoff)                                               \
    do {                                                                      \
        _Pragma("unroll")                                                     \
        for (int it = 0; it < 8; it++) {                                      \
            int idx_ = it * 256 + tid;                                        \
            int r_ = idx_ >> 4;                                               \
            int c_ = idx_ & 15;                                               \
            cpa16(sbase + ((wsoff) + r_ * WSROW + c_ * 4) * 4,                \
                  w + (size_t)(t0 + r_) * CD + (chunk) * 64 + c_ * 4);        \
        }                                                                     \
        asm volatile("cp.async.commit_group;" ::: "memory");                  \
    } while (0)

    SCF_ISSUE(0, WS0_OFF);
    SCF_ISSUE(1, WS1_OFF);

    int tok  = tid >> 1;
    int koff = (tid & 1) * 8;
    float acc[8] = {};

    for (int c = 0; c < NCHUNK; c++) {
        if (c == NCHUNK - 1)
            asm volatile("cp.async.wait_group 0;" ::: "memory");
        else
            asm volatile("cp.async.wait_group 1;" ::: "memory");
        __syncthreads();
        const float* wr = sm + ((c & 1) ? WS1_OFF : WS0_OFF) + tok * WSROW;
        const float* qrow = sm + c * 64 * CK + koff;
#pragma unroll 8
        for (int d = 0; d < 64; d++) {
            float a = wr[d];
            float4 q0 = *(const float4*)(qrow + d * CK);
            float4 q1 = *(const float4*)(qrow + d * CK + 4);
            acc[0] += a * q0.x; acc[1] += a * q0.y;
            acc[2] += a * q0.z; acc[3] += a * q0.w;
            acc[4] += a * q1.x; acc[5] += a * q1.y;
            acc[6] += a * q1.z; acc[7] += a * q1.w;
        }
        __syncthreads();
        if (c + 2 < NCHUNK) SCF_ISSUE(c + 2, (c & 1) ? WS1_OFF : WS0_OFF);
    }
#undef SCF_ISSUE

#pragma unroll
    for (int kk = 0; kk < 8; kk++) acc[kk] += sm[OFF_OFF + koff + kk];

    int bn = t0 + tok;
    if (mask[bn] == 0) {
        float4 u = make_float4(1.f / CK, 1.f / CK, 1.f / CK, 1.f / CK);
        *(float4*)(S + (size_t)bn * CK + koff) = u;
        *(float4*)(S + (size_t)bn * CK + koff + 4) = u;
    } else {
        const float scale = rsqrtf((float)(CDn / 8));
        float m = acc[0];
#pragma unroll
        for (int kk = 1; kk < 8; kk++) m = fmaxf(m, acc[kk]);
        m = fmaxf(m, __shfl_xor_sync(0xffffffffu, m, 1));
        float e[8], s = 0.f;
#pragma unroll
        for (int kk = 0; kk < 8; kk++) { e[kk] = __expf((acc[kk] - m) * scale); s += e[kk]; }
        s += __shfl_xor_sync(0xffffffffu, s, 1);
        float inv = 1.f / s;
        float4 o0 = make_float4(e[0] * inv, e[1] * inv, e[2] * inv, e[3] * inv);
        float4 o1 = make_float4(e[4] * inv, e[5] * inv, e[6] * inv, e[7] * inv);
        *(float4*)(S + (size_t)bn * CK + koff) = o0;
        *(float4*)(S + (size_t)bn * CK + koff + 4) = o1;
    }
}

// ------- U[b,k,:] = sum_n S[b,n,k] * w[b,n,:]  (+ sumS); write bf16 limbs ---
__global__ void uagg_kernel(const float* __restrict__ S, const float* __restrict__ w,
                            __nv_bfloat16* __restrict__ uh, __nv_bfloat16* __restrict__ ul,
                            float* __restrict__ sumS)
{
    int b = blockIdx.y;
    int d0 = blockIdx.x * 128;
    __shared__ float Ss[CN * CK];
    __shared__ float ws[7 * 128];
    for (int i = threadIdx.x; i < CN * CK; i += 256)
        Ss[i] = S[(size_t)b * CN * CK + i];
    int k  = threadIdx.x >> 4;
    int ds = threadIdx.x & 15;
    float acc[8] = {};
    float ssum = 0.f;
    for (int n0 = 0; n0 < CN; n0 += 7) {
        __syncthreads();
        for (int i = threadIdx.x; i < 7 * 128; i += 256) {
            int nn = i >> 7, dd = i & 127;
            ws[i] = w[((size_t)b * CN + n0 + nn) * CD + d0 + dd];
        }
        __syncthreads();
#pragma unroll
        for (int j = 0; j < 7; j++) {
            float sv = Ss[(n0 + j) * CK + k];
            ssum += sv;
#pragma unroll
            for (int c = 0; c < 8; c++) acc[c] += sv * ws[j * 128 + ds + 16 * c];
        }
    }
#pragma unroll
    for (int c = 0; c < 8; c++) {
        size_t o = ((size_t)b * CK + k) * CDn + d0 + ds + 16 * c;
        __nv_bfloat16 h, l;
        split_bf16(acc[c], h, l);
        uh[o] = h; ul[o] = l;
    }
    if (blockIdx.x == 0 && ds == 0) sumS[b * CK + k] = ssum;
}

// ------- all 5 weight matrices transposed + split to bf16 limbs -------------
__global__ void split_weights(const float* __restrict__ Wv, const float* __restrict__ We1,
                              const float* __restrict__ Wg,
                              __nv_bfloat16* __restrict__ dh, __nv_bfloat16* __restrict__ dl) {
    int z = blockIdx.z;
    const float* src; int ld, ncols, dsto;
    switch (z) {
        case 0: src = Wv;                        ld = 768; ncols = 768; dsto = 0;    break;
        case 1: src = We1;                       ld = 512; ncols = 512; dsto = 768;  break;
        case 2: src = We1 + (size_t)768 * 512;   ld = 512; ncols = 512; dsto = 1280; break;
        case 3: src = Wg;                        ld = 768; ncols = 768; dsto = 1792; break;
        default: src = Wg + (size_t)768 * 768;   ld = 768; ncols = 768; dsto = 2560; break;
    }
    int n0 = blockIdx.x * 32, k0 = blockIdx.y * 32;
    if (n0 >= ncols) return;
    __shared__ float t[32][33];
    int tx = threadIdx.x, ty = threadIdx.y;
#pragma unroll
    for (int j = 0; j < 4; j++)
        t[ty + 8 * j][tx] = src[(size_t)(k0 + ty + 8 * j) * ld + n0 + tx];
    __syncthreads();
#pragma unroll
    for (int j = 0; j < 4; j++) {
        float x = t[tx][ty + 8 * j];
        __nv_bfloat16 h, l;
        split_bf16(x, h, l);
        size_t o = (size_t)(dsto + n0 + ty + 8 * j) * GK + k0 + tx;
        dh[o] = h;
        dl[o] = l;
    }
}

// ---------------- mma.sync split-bf16 GEMM, 64x64 tiles, 128 threads --------
// 2 CTAs/SM (96 KB smem) to smooth wave tails.
__global__ void __launch_bounds__(128, 2) gemm_mma(
    const __nv_bfloat16* __restrict__ Ah, const __nv_bfloat16* __restrict__ Al,
    const __nv_bfloat16* __restrict__ Bh, const __nv_bfloat16* __restrict__ Bl,
    const float* __restrict__ bias, float* __restrict__ C, int Nn)
{
    extern __shared__ char smem[];
    const uint32_t sbase = smem_u32(smem);
    const int tid = threadIdx.x;
    const int lane = tid & 31, wid = tid >> 5;
    const int warp_m = wid >> 1, warp_n = wid & 1;   // 2 x 2 warp grid, warp tile 32x32
    const int row0 = blockIdx.y * 64;
    const int col0 = blockIdx.x * 64;

    float acc[2][4][4];
#pragma unroll
    for (int a = 0; a < 2; a++)
#pragma unroll
        for (int b = 0; b < 4; b++)
#pragma unroll
            for (int c = 0; c < 4; c++) acc[a][b][c] = 0.f;

#define ISSUE_CHUNK(chunk, buf)                                                     \
    do {                                                                            \
        uint32_t bufo_ = sbase + (buf) * BUFB;                                      \
        _Pragma("unroll")                                                           \
        for (int it = 0; it < 16; it++) {                                           \
            int idx_ = it * 128 + tid;                                              \
            int t_ = idx_ >> 9;                                                     \
            int r_ = (idx_ >> 3) & 63;                                              \
            int c_ = idx_ & 7;                                                      \
            const __nv_bfloat16* sp_ =                                              \
                (t_ == 0) ? Ah + (size_t)(row0 + r_) * GK :                         \
                (t_ == 1) ? Al + (size_t)(row0 + r_) * GK :                         \
                (t_ == 2) ? Bh + (size_t)(col0 + r_) * GK :                         \
                            Bl + (size_t)(col0 + r_) * GK;                          \
            sp_ += (chunk) * KCH + c_ * 8;                                          \
            uint32_t sa_ = bufo_ + t_ * TILEB + r_ * 128 + ((c_ ^ (r_ & 7)) << 4);  \
            cpa16(sa_, sp_);                                                        \
        }                                                                           \
        asm volatile("cp.async.commit_group;" ::: "memory");                        \
    } while (0)

    ISSUE_CHUNK(0, 0);
    ISSUE_CHUNK(1, 1);

    const int rA  = warp_m * 32 + (lane & 15);
    const int khA = lane >> 4;
    const int rB  = warp_n * 32 + (lane & 7) + ((lane >> 4) << 3);
    const int khB = (lane >> 3) & 1;
    const int swA = rA & 7, swB = rB & 7;

    for (int i = 0; i < NCHUNK; i++) {
        if (i + 2 < NCHUNK) {
            ISSUE_CHUNK(i + 2, (i + 2) % NSTAGE);
            asm volatile("cp.async.wait_group 2;" ::: "memory");
        } else if (i + 1 < NCHUNK) {
            asm volatile("cp.async.wait_group 1;" ::: "memory");
        } else {
            asm volatile("cp.async.wait_group 0;" ::: "memory");
        }
        __syncthreads();
        uint32_t bufo = sbase + (i % NSTAGE) * BUFB;
#pragma unroll
        for (int kk = 0; kk < 4; kk++) {
            uint32_t a[2][2][4];   // [limb][mtile][reg]
            uint32_t b[2][2][4];   // [limb][ntile16][reg]
            int ckA = kk * 2 + khA;
            int ckB = kk * 2 + khB;
#pragma unroll
            for (int mt = 0; mt < 2; mt++) {
                uint32_t ad = bufo + (rA + mt * 16) * 128 + (((ckA ^ swA)) << 4);
                ldsm4(a[0][mt], ad);
                ldsm4(a[1][mt], ad + TILEB);
            }
#pragma unroll
            for (int nt = 0; nt < 2; nt++) {
                uint32_t bd = bufo + 2 * TILEB + (rB + nt * 16) * 128 + (((ckB ^ swB)) << 4);
                ldsm4(b[0][nt], bd);
                ldsm4(b[1][nt], bd + TILEB);
            }
#pragma unroll
            for (int mt = 0; mt < 2; mt++)
#pragma unroll
                for (int ng = 0; ng < 4; ng++) {
                    uint32_t b0h = b[0][ng >> 1][(ng & 1) * 2 + 0];
                    uint32_t b1h = b[0][ng >> 1][(ng & 1) * 2 + 1];
                    uint32_t b0l = b[1][ng >> 1][(ng & 1) * 2 + 0];
                    uint32_t b1l = b[1][ng >> 1][(ng & 1) * 2 + 1];
                    mma16816(acc[mt][ng], a[0][mt], b0h, b1h);   // Ah*Bh
                    mma16816(acc[mt][ng], a[0][mt], b0l, b1l);   // Ah*Bl
                    mma16816(acc[mt][ng], a[1][mt], b0h, b1h);   // Al*Bh
                }
        }
        __syncthreads();
    }

    const int rowE = row0 + warp_m * 32 + (lane >> 2);
#pragma unroll
    for (int mt = 0; mt < 2; mt++) {
#pragma unroll
        for (int ng = 0; ng < 4; ng++) {
            int col = col0 + warp_n * 32 + ng * 8 + 2 * (lane & 3);
            float b0 = bias ? bias[col + 0] : 0.f;
            float b1 = bias ? bias[col + 1] : 0.f;
            float2 v0 = make_float2(acc[mt][ng][0] + b0, acc[mt][ng][1] + b1);
            float2 v1 = make_float2(acc[mt][ng][2] + b0, acc[mt][ng][3] + b1);
            *(float2*)(C + (size_t)(rowE + mt * 16) * Nn + col) = v0;
            *(float2*)(C + (size_t)(rowE + mt * 16 + 8) * Nn + col) = v1;
        }
    }
#undef ISSUE_CHUNK
}

// ------- V = (1-g)*(Cv + sumS*bv) + g*nq; write fp32 V + bf16 limbs ---------
__global__ void gate_split(const float* __restrict__ Cv, const float* __restrict__ sumS,
                           const float* __restrict__ bv, const float* __restrict__ nq,
                           const float* __restrict__ fg, float* __restrict__ V,
                           __nv_bfloat16* __restrict__ vh, __nv_bfloat16* __restrict__ vl)
{
    int i4 = blockIdx.x * 256 + threadIdx.x;
    if (i4 >= CB * CK * CDn / 4) return;
    int base = i4 * 4;
    int row = base / CDn;
    int col = base % CDn;
    int k = row & 15;
    float g = 1.f / (1.f + __expf(-fg[0]));
    float ss = sumS[row];
    float4 c = ((const float4*)Cv)[i4];
    float4 b = *(const float4*)(bv + col);
    float4 q = *(const float4*)(nq + k * CDn + col);
    float4 v;
    v.x = (1.f - g) * (c.x + ss * b.x) + g * q.x;
    v.y = (1.f - g) * (c.y + ss * b.y) + g * q.y;
    v.z = (1.f - g) * (c.z + ss * b.z) + g * q.z;
    v.w = (1.f - g) * (c.w + ss * b.w) + g * q.w;
    ((float4*)V)[i4] = v;
    __nv_bfloat16 h0, h1, h2, h3, l0, l1, l2, l3;
    split_bf16(v.x, h0, l0); split_bf16(v.y, h1, l1);
    split_bf16(v.z, h2, l2); split_bf16(v.w, h3, l3);
    ((__nv_bfloat162*)vh)[2 * i4 + 0] = __nv_bfloat162(h0, h1);
    ((__nv_bfloat162*)vh)[2 * i4 + 1] = __nv_bfloat162(h2, h3);
    ((__nv_bfloat162*)vl)[2 * i4 + 0] = __nv_bfloat162(l0, l1);
    ((__nv_bfloat162*)vl)[2 * i4 + 1] = __nv_bfloat162(l2, l3);
}

// ---------------- edge reduce on merged H [4096, 1024] ----------------------
#define LDH (2 * CHID)
template <bool DO_SOFTMAX>
__global__ void edge_kernel(const float* __restrict__ H,
                            const float* __restrict__ be1, const float* __restrict__ We2,
                            const float* __restrict__ be2, float* __restrict__ out)
{
    extern __shared__ float sm[];
    float* HIs  = sm;
    float* HJs  = HIs + CHID * CK;
    float* be1s = HJs + CHID * CK;
    float* we2s = be1s + CHID;
    float* Es   = we2s + CHID;
    int b = blockIdx.x;
    for (int idx = threadIdx.x; idx < CK * CHID; idx += 256) {
        int i = idx / CHID, h = idx % CHID;
        HIs[h * CK + i] = H[((size_t)b * CK + i) * LDH + h];
        HJs[h * CK + i] = H[((size_t)b * CK + i) * LDH + CHID + h];
    }
    for (int idx = threadIdx.x; idx < CHID; idx += 256) {
        be1s[idx] = be1[idx];
        we2s[idx] = We2[idx];
    }
    __syncthreads();
    int i = threadIdx.x >> 4, j = threadIdx.x & 15;
    float acc = be2[0];
#pragma unroll 4
    for (int h = 0; h < CHID; h++) {
        float v = HIs[h * CK + i] + HJs[h * CK + j] + be1s[h];
        acc += fmaxf(v, 0.f) * we2s[h];
    }
    if (!DO_SOFTMAX) {
        out[(size_t)b * CK * CK + i * CK + j] = acc;
    } else {
        Es[i * CK + j] = acc;
        __syncthreads();
        float m = -INFINITY;
#pragma unroll
        for (int jj = 0; jj < CK; jj++) m = fmaxf(m, Es[i * CK + jj]);
        float ssum = 0.f;
#pragma unroll
        for (int jj = 0; jj < CK; jj++) ssum += __expf(Es[i * CK + jj] - m);
        out[(size_t)b * CK * CK + i * CK + j] = __expf(acc - m) / ssum;
    }
}

// ------- GNN update + bf16 split ---------------------------------------------
__global__ void gnn_update(const float* __restrict__ A, const float* __restrict__ M,
                           float* __restrict__ V,
                           __nv_bfloat16* __restrict__ vh, __nv_bfloat16* __restrict__ vl)
{
    int b = blockIdx.y;
    int d0 = blockIdx.x * 128;
    __shared__ float As[CK * CK];
    __shared__ float Ms[CK * 128];
    for (int idx = threadIdx.x; idx < CK * CK; idx += 256)
        As[idx] = A[(size_t)b * CK * CK + idx];
    for (int idx = threadIdx.x; idx < CK * 128; idx += 256) {
        int j = idx >> 7, dd = idx & 127;
        Ms[idx] = M[((size_t)b * CK + j) * CDn + d0 + dd];
    }
    __syncthreads();
    int i  = threadIdx.x >> 4;
    int ds = threadIdx.x & 15;
    float acc[8] = {};
#pragma unroll
    for (int j = 0; j < CK; j++) {
        float a = As[i * CK + j];
#pragma unroll
        for (int c = 0; c < 8; c++) acc[c] += a * Ms[j * 128 + ds + 16 * c];
    }
#pragma unroll
    for (int c = 0; c < 8; c++) {
        size_t o = ((size_t)b * CK + i) * CDn + d0 + ds + 16 * c;
        float v = V[o] + fmaxf(acc[c], 0.f);
        V[o] = v;
        __nv_bfloat16 h, l;
        split_bf16(v, h, l);
        vh[o] = h; vl[o] = l;
    }
}

// ---------------------------------------------------------------------------
extern "C" void kernel_launch(void* const* d_in, const int* in_sizes, int n_in,
                              void* d_out, int out_size)
{
    const float* w    = (const float*)d_in[0];
    const int*   mask = (const int*)  d_in[1];
    const float* nq   = (const float*)d_in[2];
    const float* Wq   = (const float*)d_in[3];
    const float* bq   = (const float*)d_in[4];
    const float* Wk   = (const float*)d_in[5];
    const float* bk   = (const float*)d_in[6];
    const float* Wv   = (const float*)d_in[7];
    const float* bv   = (const float*)d_in[8];
    const float* We1  = (const float*)d_in[9];
    const float* be1  = (const float*)d_in[10];
    const float* We2  = (const float*)d_in[11];
    const float* be2  = (const float*)d_in[12];
    const float* fg   = (const float*)d_in[13];
    const float* Wg   = (const float*)d_in[14];
    const float* bg   = (const float*)d_in[15];

    float* S = (float*)d_out;                       // [B,N,K]
    float* V = S + (size_t)CB * CN * CK;            // [B,K,Dn]
    float* E = V + (size_t)CB * CK * CDn;           // [B,K,K]

    float *Qb, *Qp, *QKTt, *off, *sumS, *Ab, *Hb, *Mg;
    __nv_bfloat16 *uh, *ul, *vh, *vl, *Wth, *Wtl;
    cudaGetSymbolAddress((void**)&Qb,   g_Q);
    cudaGetSymbolAddress((void**)&Qp,   g_Qp);
    cudaGetSymbolAddress((void**)&QKTt, g_QKTt);
    cudaGetSymbolAddress((void**)&off,  g_off);
    cudaGetSymbolAddress((void**)&sumS, g_sumS);
    cudaGetSymbolAddress((void**)&Ab,   g_A);
    cudaGetSymbolAddress((void**)&Hb,   g_H);
    cudaGetSymbolAddress((void**)&Mg,   g_Mg);
    cudaGetSymbolAddress((void**)&uh,   g_uh);
    cudaGetSymbolAddress((void**)&ul,   g_ul);
    cudaGetSymbolAddress((void**)&vh,   g_vh);
    cudaGetSymbolAddress((void**)&vl,   g_vl);
    cudaGetSymbolAddress((void**)&Wth,  g_Wth);
    cudaGetSymbolAddress((void**)&Wtl,  g_Wtl);

    const int EDGE_SMEM = (2 * CHID * CK + 2 * CHID + CK * CK) * (int)sizeof(float);
    cudaFuncSetAttribute(edge_kernel<true>,  cudaFuncAttributeMaxDynamicSharedMemorySize, EDGE_SMEM);
    cudaFuncSetAttribute(edge_kernel<false>, cudaFuncAttributeMaxDynamicSharedMemorySize, EDGE_SMEM);
    cudaFuncSetAttribute(gemm_mma, cudaFuncAttributeMaxDynamicSharedMemorySize, GSMEM);
    cudaFuncSetAttribute(scores_fast, cudaFuncAttributeMaxDynamicSharedMemorySize, SCF_SMEM);

    const int Mtok = CB * CN;   // 19712
    const int Mkv  = CB * CK;   // 4096
    dim3 tb(32, 8);

    // 1-2. Q = nq @ Wq + bq (batch-invariant)
    q_partial<<<dim3(CDn / 128, 8), 128>>>(nq, Wq, Qp);
    q_reduce<<<(CK * CDn + 255) / 256, 256>>>(Qp, bq, Qb);
    // 3. QKT^T = (Q @ Wk^T)^T, off = Q @ bk
    qk_kernel<<<CD + 1, 256>>>(Qb, Wk, bk, QKTt, off);
    // 4. fast fused scores + masked softmax  <-- profiled launch
    scores_fast<<<Mtok / 128, 256, SCF_SMEM>>>(w, QKTt, off, mask, S);
    // 5. U = S^T w (per batch) + sumS, split to bf16 limbs
    uagg_kernel<<<dim3(CDn / 128, CB), 256>>>(S, w, uh, ul, sumS);
    // 6. weight transpose+split
    split_weights<<<dim3(24, 24, 5), tb>>>(Wv, We1, Wg, Wth, Wtl);
    // 7. Cv = U @ Wv
    gemm_mma<<<dim3(CDn / 64, Mkv / 64), 128, GSMEM>>>(uh, ul, Wth, Wtl, nullptr, Mg, CDn);
    // 8. V = (1-g)(Cv + sumS*bv) + g*nq; split
    gate_split<<<(Mkv * CDn / 4 + 255) / 256, 256>>>(Mg, sumS, bv, nq, fg, V, vh, vl);

    // 9-10. pre-GNN edge logits (merged Hi|Hj GEMM) -> A = softmax(E)
    gemm_mma<<<dim3(2 * CHID / 64, Mkv / 64), 128, GSMEM>>>(vh, vl, Wth + (size_t)768 * GK,
                                                            Wtl + (size_t)768 * GK, nullptr, Hb, LDH);
    edge_kernel<true><<<CB, 256, EDGE_SMEM>>>(Hb, be1, We2, be2, Ab);

    // 11-14. GNN layers
    for (int l = 0; l < CL; l++) {
        gemm_mma<<<dim3(CDn / 64, Mkv / 64), 128, GSMEM>>>(
            vh, vl, Wth + (size_t)(1792 + 768 * l) * GK, Wtl + (size_t)(1792 + 768 * l) * GK,
            bg + (size_t)l * CDn, Mg, CDn);
        gnn_update<<<dim3(CDn / 128, CB), 256>>>(Ab, Mg, V, vh, vl);
    }

    // 15-16. post-GNN edge logits -> E (output)
    gemm_mma<<<dim3(2 * CHID / 64, Mkv / 64), 128, GSMEM>>>(vh, vl, Wth + (size_t)768 * GK,
                                                            Wtl + (size_t)768 * GK, nullptr, Hb, LDH);
    edge_kernel<false><<<CB, 256, EDGE_SMEM>>>(Hb, be1, We2, be2, E);
}